// round 1
// baseline (speedup 1.0000x reference)
#include <cuda_runtime.h>
#include <math.h>

#define N_NAMED 8000
#define ANON_E 192
#define N_TOTAL 8192
#define DIM 128
#define BLOCKS_A 64
#define THREADS_A 256                      // 8 warps
#define WARPS_A (THREADS_A / 32)
#define ROWS_PER_WARP (N_TOTAL / (BLOCKS_A * WARPS_A))   // 16

// Scratch (no cudaMalloc allowed): dl[i] = e_i . w_l ; per-block partial max of e_i . w_r
__device__ float g_dl[N_TOTAL];
__device__ float g_pmax[BLOCKS_A];

__global__ void __launch_bounds__(THREADS_A)
dots_kernel(const float* __restrict__ anon,
            const float* __restrict__ etab,
            const float* __restrict__ w)   // fc0_w: [0..127]=w_l, [128..255]=w_r
{
    __shared__ float s_w[2 * DIM];
    __shared__ float s_max[WARPS_A];

    int tid = threadIdx.x;
    s_w[tid] = w[tid];                     // 256 threads load 256 weights
    __syncthreads();

    int warp = tid >> 5;
    int lane = tid & 31;

    // each lane owns 4 contiguous dims
    float4 wl = reinterpret_cast<const float4*>(s_w)[lane];
    float4 wr = reinterpret_cast<const float4*>(s_w + DIM)[lane];

    float local_max = -3.4e38f;
    int base = (blockIdx.x * WARPS_A + warp) * ROWS_PER_WARP;

#pragma unroll 4
    for (int r = base; r < base + ROWS_PER_WARP; ++r) {
        const float* e = (r < N_NAMED)
                           ? (etab + (size_t)r * DIM)
                           : (anon + (size_t)(r - N_NAMED) * DIM);
        float4 v = reinterpret_cast<const float4*>(e)[lane];
        float dl = v.x * wl.x + v.y * wl.y + v.z * wl.z + v.w * wl.w;
        float dr = v.x * wr.x + v.y * wr.y + v.z * wr.z + v.w * wr.w;
#pragma unroll
        for (int o = 16; o > 0; o >>= 1) {
            dl += __shfl_down_sync(0xffffffffu, dl, o);
            dr += __shfl_down_sync(0xffffffffu, dr, o);
        }
        if (lane == 0) {
            g_dl[r] = dl;
            local_max = fmaxf(local_max, dr);
        }
    }
    if (lane == 0) s_max[warp] = local_max;
    __syncthreads();
    if (tid == 0) {
        float m = s_max[0];
#pragma unroll
        for (int i = 1; i < WARPS_A; ++i) m = fmaxf(m, s_max[i]);
        g_pmax[blockIdx.x] = m;
    }
}

__global__ void __launch_bounds__(256)
out_kernel(const float* __restrict__ ctab,
           const float* __restrict__ rtab,
           const float* __restrict__ w,
           const float* __restrict__ bptr,
           const int*   __restrict__ cid,
           const int*   __restrict__ rid,
           float*       __restrict__ out)
{
    __shared__ float s_vals[3];            // col_max, c_dot, r_dot
    int tid = threadIdx.x;

    if (tid < 32) {
        int lane = tid;
        // reduce 64 per-block partial maxes (each block does this redundantly;
        // 64 floats from L2 — cheaper than a 3rd kernel launch)
        float m = fmaxf(g_pmax[lane], g_pmax[lane + 32]);

        const float* ce = ctab + (size_t)(*cid) * DIM;
        const float* re = rtab + (size_t)(*rid) * DIM;
        float cd = 0.f, rd = 0.f;
#pragma unroll
        for (int k = 0; k < 4; ++k) {
            float wlv = __ldg(&w[lane * 4 + k]);     // w_l only
            cd += __ldg(&ce[lane * 4 + k]) * wlv;
            rd += __ldg(&re[lane * 4 + k]) * wlv;
        }
#pragma unroll
        for (int o = 16; o > 0; o >>= 1) {
            m  = fmaxf(m, __shfl_down_sync(0xffffffffu, m, o));
            cd += __shfl_down_sync(0xffffffffu, cd, o);
            rd += __shfl_down_sync(0xffffffffu, rd, o);
        }
        if (lane == 0) { s_vals[0] = m; s_vals[1] = cd; s_vals[2] = rd; }
    }
    __syncthreads();

    float cmax  = s_vals[0];
    float c_dot = s_vals[1];
    float r_dot = s_vals[2];
    float b     = *bptr;

    int i = blockIdx.x * blockDim.x + tid;
    // Exact collapse of max_j sigma(row_i+col_j+b)*sigma(c_dot+col_j+b):
    // both factors strictly increase in col_j -> argmax at col_max.
    float cfs = 1.f / (1.f + expf(-(c_dot + cmax + b)));
    float rfs = 1.f / (1.f + expf(-(g_dl[i] + r_dot + cmax + b)));
    out[i] = rfs * cfs;
}

extern "C" void kernel_launch(void* const* d_in, const int* in_sizes, int n_in,
                              void* d_out, int out_size) {
    const float* anon = (const float*)d_in[0];   // [192,128]
    const float* etab = (const float*)d_in[1];   // [8000,128]
    const float* ctab = (const float*)d_in[2];   // [100,128]
    const float* rtab = (const float*)d_in[3];   // [50,128]
    const float* w    = (const float*)d_in[4];   // [1,256]
    const float* bb   = (const float*)d_in[5];   // [1]
    const int*   cid  = (const int*)d_in[6];
    const int*   rid  = (const int*)d_in[7];
    float* out = (float*)d_out;                  // [8192]

    dots_kernel<<<BLOCKS_A, THREADS_A>>>(anon, etab, w);
    out_kernel<<<N_TOTAL / 256, 256>>>(ctab, rtab, w, bb, cid, rid, out);
}